// round 11
// baseline (speedup 1.0000x reference)
#include <cuda_runtime.h>
#include <math.h>
#include <stdint.h>

// InputLayer: out[b,n,d] = LN_d( (x[b,n]*W[d] + bias[d]) * sqrt(1024) ) * gamma[d] + beta[d]
// Analytic LayerNorm (h affine in a=x[b,n]) -> closed-form stats of (W,b).
// R11: R3 schedule (grid=1024, 64 rows/block, 256 threads) but with Blackwell
// 256-bit stores (st.global.cs.v8.f32): 256 threads = 2 rows x 128 col-groups
// of 8 floats -> half the store instructions, 1KB contiguous per warp-store.

#define SIZE 1024
#define VEC 8
#define CG  (SIZE / VEC)          // 128 column groups
#define TPB 256                   // 2 rows x 128 groups
#define RPB 64                    // rows per block
#define LN_EPS 1e-5f

__global__ __launch_bounds__(TPB)
void il_fused_kernel(const float* __restrict__ x,
                     const float* __restrict__ W,
                     const float* __restrict__ B,
                     const float* __restrict__ G,
                     const float* __restrict__ Be,
                     float* __restrict__ out,
                     int nrows) {
    const float SCALE = 32.0f;                 // sqrt(1024)
    const float S2 = SCALE * SCALE;

    int q  = threadIdx.x;                      // 0..255
    int c  = q & (CG - 1);                     // column group 0..127
    int rr = q >> 7;                           // row parity 0/1
    int d0 = c * VEC;
    int row0 = blockIdx.x * RPB;

    __shared__ float xa[RPB];
    __shared__ float red[5][8];                // 5 stats x 8 warps

    if (q < RPB) {
        int r = row0 + q;
        xa[q] = (r < nrows) ? x[r] : 0.0f;
    }

    float w[VEC], b[VEC], g[VEC], be[VEC];
    {
        float4 t0 = *(const float4*)(W  + d0);
        float4 t1 = *(const float4*)(W  + d0 + 4);
        w[0]=t0.x; w[1]=t0.y; w[2]=t0.z; w[3]=t0.w;
        w[4]=t1.x; w[5]=t1.y; w[6]=t1.z; w[7]=t1.w;
        t0 = *(const float4*)(B + d0); t1 = *(const float4*)(B + d0 + 4);
        b[0]=t0.x; b[1]=t0.y; b[2]=t0.z; b[3]=t0.w;
        b[4]=t1.x; b[5]=t1.y; b[6]=t1.z; b[7]=t1.w;
        t0 = *(const float4*)(G + d0); t1 = *(const float4*)(G + d0 + 4);
        g[0]=t0.x; g[1]=t0.y; g[2]=t0.z; g[3]=t0.w;
        g[4]=t1.x; g[5]=t1.y; g[6]=t1.z; g[7]=t1.w;
        t0 = *(const float4*)(Be + d0); t1 = *(const float4*)(Be + d0 + 4);
        be[0]=t0.x; be[1]=t0.y; be[2]=t0.z; be[3]=t0.w;
        be[4]=t1.x; be[5]=t1.y; be[6]=t1.z; be[7]=t1.w;
    }

    // ---- stats: each column is covered by exactly 2 threads -> sums are 2x,
    // normalize by 1/(2*SIZE). ----
    float s0 = 0.f, s1 = 0.f, s2 = 0.f, s3 = 0.f, s4 = 0.f;
    #pragma unroll
    for (int i = 0; i < VEC; i++) {
        s0 += w[i];        s1 += b[i];
        s2 += w[i] * w[i]; s3 += b[i] * b[i];
        s4 += w[i] * b[i];
    }

    int lane = q & 31, warp = q >> 5;
    #pragma unroll
    for (int o = 16; o > 0; o >>= 1) {
        s0 += __shfl_down_sync(0xffffffffu, s0, o);
        s1 += __shfl_down_sync(0xffffffffu, s1, o);
        s2 += __shfl_down_sync(0xffffffffu, s2, o);
        s3 += __shfl_down_sync(0xffffffffu, s3, o);
        s4 += __shfl_down_sync(0xffffffffu, s4, o);
    }
    if (lane == 0) {
        red[0][warp] = s0; red[1][warp] = s1; red[2][warp] = s2;
        red[3][warp] = s3; red[4][warp] = s4;
    }
    __syncthreads();

    float t0 = 0.f, t1 = 0.f, t2 = 0.f, t3 = 0.f, t4 = 0.f;
    #pragma unroll
    for (int i = 0; i < 8; i++) {
        t0 += red[0][i]; t1 += red[1][i]; t2 += red[2][i];
        t3 += red[3][i]; t4 += red[4][i];
    }
    const float inv = 1.0f / (float)(2 * SIZE); // columns double-counted
    float mw = t0 * inv, mb = t1 * inv;
    float vw = fmaf(-mw, mw, t2 * inv);        // Var(W)
    float vb = fmaf(-mb, mb, t3 * inv);        // Var(B)
    float cv = fmaf(-mw, mb, t4 * inv);        // Cov(W,B)

    // P = (W - meanW) * gamma ;  Q = (B - meanB) * gamma
    float P[VEC], Q[VEC];
    #pragma unroll
    for (int i = 0; i < VEC; i++) {
        P[i] = (w[i] - mw) * g[i];
        Q[i] = (b[i] - mb) * g[i];
    }

    __syncthreads();

    int rmax = nrows - row0;
    if (rmax > RPB) rmax = RPB;

    const float* obase = out + (size_t)row0 * SIZE + d0;

    #pragma unroll 4
    for (int r = rr; r < rmax; r += 2) {
        float a = xa[r];
        float var = S2 * fmaf(a, fmaf(a, vw, 2.0f * cv), vb);
        float t = SCALE * rsqrtf(var + LN_EPS);
        float c0 = t * a;

        float o0 = fmaf(c0, P[0], fmaf(t, Q[0], be[0]));
        float o1 = fmaf(c0, P[1], fmaf(t, Q[1], be[1]));
        float o2 = fmaf(c0, P[2], fmaf(t, Q[2], be[2]));
        float o3 = fmaf(c0, P[3], fmaf(t, Q[3], be[3]));
        float o4 = fmaf(c0, P[4], fmaf(t, Q[4], be[4]));
        float o5 = fmaf(c0, P[5], fmaf(t, Q[5], be[5]));
        float o6 = fmaf(c0, P[6], fmaf(t, Q[6], be[6]));
        float o7 = fmaf(c0, P[7], fmaf(t, Q[7], be[7]));

        const float* dst = obase + (size_t)r * SIZE;
        asm volatile(
            "st.global.cs.v8.f32 [%0], {%1,%2,%3,%4,%5,%6,%7,%8};"
            :: "l"(dst),
               "f"(o0), "f"(o1), "f"(o2), "f"(o3),
               "f"(o4), "f"(o5), "f"(o6), "f"(o7)
            : "memory");
    }
}

extern "C" void kernel_launch(void* const* d_in, const int* in_sizes, int n_in,
                              void* d_out, int out_size) {
    const float* x  = (const float*)d_in[0];   // (2048, 32)
    const float* W  = (const float*)d_in[1];   // (1024, 1)
    const float* B  = (const float*)d_in[2];   // (1024,)
    const float* G  = (const float*)d_in[3];   // (1024,)
    const float* Be = (const float*)d_in[4];   // (1024,)
    float* out = (float*)d_out;

    int nrows = in_sizes[0];                   // 65536 rows

    int grid = (nrows + RPB - 1) / RPB;        // 1024 blocks (R3 schedule)
    il_fused_kernel<<<grid, TPB>>>(x, W, B, G, Be, out, nrows);
}

// round 13
// speedup vs baseline: 1.0438x; 1.0438x over previous
#include <cuda_runtime.h>
#include <math.h>

// InputLayer: out[b,n,d] = LN_d( (x[b,n]*W[d] + bias[d]) * sqrt(1024) ) * gamma[d] + beta[d]
// Analytic LayerNorm: h is affine in a=x[b,n], so mean/var are closed-form in
// per-column stats of (W, bias). Single fused kernel: each block computes the
// tiny W/b stats itself (redundantly, from L2), then streams FMA + STG.128.
//
// FINAL (== R3, best of 8 controlled experiments): grid=1024 x 256thr,
// 64 rows/block, __stcs streaming STG.128. Sustains ~6.2 TB/s DRAM writes —
// the empirical write wall; every scheduling/store-path/width variant tested
// (R4-R11) was equal or worse.

#define SIZE 1024
#define QUADS (SIZE / 4)          // 256 threads per block
#define RPB 64                    // rows per block
#define LN_EPS 1e-5f

__global__ __launch_bounds__(QUADS)
void il_fused_kernel(const float* __restrict__ x,
                     const float* __restrict__ W,
                     const float* __restrict__ B,
                     const float* __restrict__ G,
                     const float* __restrict__ Be,
                     float* __restrict__ out,
                     int nrows) {
    const float SCALE = 32.0f;                 // sqrt(1024)
    const float S2 = SCALE * SCALE;

    int q = threadIdx.x;                       // 0..255
    int d0 = q * 4;
    int row0 = blockIdx.x * RPB;

    __shared__ float xa[RPB];
    __shared__ float red[5][8];                // 5 stats x 8 warps

    if (q < RPB) {
        int r = row0 + q;
        xa[q] = (r < nrows) ? x[r] : 0.0f;
    }

    float4 w4  = *(const float4*)(W  + d0);
    float4 b4  = *(const float4*)(B  + d0);
    float4 g4  = *(const float4*)(G  + d0);
    float4 be4 = *(const float4*)(Be + d0);

    // ---- per-block stats reduction over the 1024 (W,b) columns ----
    float s0 = w4.x + w4.y + w4.z + w4.w;                              // sum W
    float s1 = b4.x + b4.y + b4.z + b4.w;                              // sum B
    float s2 = w4.x*w4.x + w4.y*w4.y + w4.z*w4.z + w4.w*w4.w;          // sum W^2
    float s3 = b4.x*b4.x + b4.y*b4.y + b4.z*b4.z + b4.w*b4.w;          // sum B^2
    float s4 = w4.x*b4.x + w4.y*b4.y + w4.z*b4.z + w4.w*b4.w;          // sum W*B

    int lane = q & 31, warp = q >> 5;
    #pragma unroll
    for (int o = 16; o > 0; o >>= 1) {
        s0 += __shfl_down_sync(0xffffffffu, s0, o);
        s1 += __shfl_down_sync(0xffffffffu, s1, o);
        s2 += __shfl_down_sync(0xffffffffu, s2, o);
        s3 += __shfl_down_sync(0xffffffffu, s3, o);
        s4 += __shfl_down_sync(0xffffffffu, s4, o);
    }
    if (lane == 0) {
        red[0][warp] = s0; red[1][warp] = s1; red[2][warp] = s2;
        red[3][warp] = s3; red[4][warp] = s4;
    }
    __syncthreads();

    float t0 = 0.f, t1 = 0.f, t2 = 0.f, t3 = 0.f, t4 = 0.f;
    #pragma unroll
    for (int i = 0; i < 8; i++) {
        t0 += red[0][i]; t1 += red[1][i]; t2 += red[2][i];
        t3 += red[3][i]; t4 += red[4][i];
    }
    const float inv = 1.0f / (float)SIZE;
    float mw = t0 * inv, mb = t1 * inv;
    float vw = fmaf(-mw, mw, t2 * inv);        // Var(W)
    float vb = fmaf(-mb, mb, t3 * inv);        // Var(B)
    float cv = fmaf(-mw, mb, t4 * inv);        // Cov(W,B)

    // P = (W - meanW) * gamma ;  Q = (B - meanB) * gamma
    float4 P, Q;
    P.x = (w4.x - mw) * g4.x;  Q.x = (b4.x - mb) * g4.x;
    P.y = (w4.y - mw) * g4.y;  Q.y = (b4.y - mb) * g4.y;
    P.z = (w4.z - mw) * g4.z;  Q.z = (b4.z - mb) * g4.z;
    P.w = (w4.w - mw) * g4.w;  Q.w = (b4.w - mb) * g4.w;

    __syncthreads();

    int rmax = nrows - row0;
    if (rmax > RPB) rmax = RPB;

    float4* obase = (float4*)(out + (size_t)row0 * SIZE + d0);

    #pragma unroll 4
    for (int r = 0; r < rmax; r++) {
        float a = xa[r];
        float var = S2 * fmaf(a, fmaf(a, vw, 2.0f * cv), vb);
        float t = SCALE * rsqrtf(var + LN_EPS);
        float c0 = t * a;

        float4 o;
        o.x = fmaf(c0, P.x, fmaf(t, Q.x, be4.x));
        o.y = fmaf(c0, P.y, fmaf(t, Q.y, be4.y));
        o.z = fmaf(c0, P.z, fmaf(t, Q.z, be4.z));
        o.w = fmaf(c0, P.w, fmaf(t, Q.w, be4.w));

        // streaming store: output is never re-read
        __stcs(obase + (size_t)r * QUADS, o);
    }
}

extern "C" void kernel_launch(void* const* d_in, const int* in_sizes, int n_in,
                              void* d_out, int out_size) {
    const float* x  = (const float*)d_in[0];   // (2048, 32)
    const float* W  = (const float*)d_in[1];   // (1024, 1)
    const float* B  = (const float*)d_in[2];   // (1024,)
    const float* G  = (const float*)d_in[3];   // (1024,)
    const float* Be = (const float*)d_in[4];   // (1024,)
    float* out = (float*)d_out;

    int nrows = in_sizes[0];                   // 65536 rows

    int grid = (nrows + RPB - 1) / RPB;        // 1024 blocks
    il_fused_kernel<<<grid, QUADS>>>(x, W, B, G, Be, out, nrows);
}